// round 14
// baseline (speedup 1.0000x reference)
#include <cuda_runtime.h>
#include <cuda_fp16.h>
#include <cstdint>

#define BB 16
#define TT 2048
#define CC 1024
#define HH 64
#define NROWS (BB * TT)

// QKV scratch, single fp16, packed 2 per uint32: [B*T][96] uint32
//   q: cols 0..31, k: 32..63, v: 64..95
__device__ uint32_t g_qkv32[(size_t)NROWS * 96];
// W transposed, single fp16: [192][1024]
__device__ __half g_wt16[192 * CC];

// ---------------------------------------------------------------------------
// helpers (sm_80+ baseline ISA)
// ---------------------------------------------------------------------------
__device__ __forceinline__ uint32_t smem_u32(const void* p) {
  return (uint32_t)__cvta_generic_to_shared(p);
}
__device__ __forceinline__ void ldsm_x4(uint32_t* r, uint32_t addr) {
  asm volatile("ldmatrix.sync.aligned.m8n8.x4.shared.b16 {%0,%1,%2,%3}, [%4];"
               : "=r"(r[0]), "=r"(r[1]), "=r"(r[2]), "=r"(r[3]) : "r"(addr));
}
__device__ __forceinline__ void ldsm_x4_t(uint32_t* r, uint32_t addr) {
  asm volatile("ldmatrix.sync.aligned.m8n8.x4.trans.shared.b16 {%0,%1,%2,%3}, [%4];"
               : "=r"(r[0]), "=r"(r[1]), "=r"(r[2]), "=r"(r[3]) : "r"(addr));
}
__device__ __forceinline__ void mma_f16(float* c, const uint32_t* a,
                                        uint32_t b0, uint32_t b1) {
  asm volatile(
      "mma.sync.aligned.m16n8k16.row.col.f32.f16.f16.f32 "
      "{%0,%1,%2,%3}, {%4,%5,%6,%7}, {%8,%9}, {%0,%1,%2,%3};"
      : "+f"(c[0]), "+f"(c[1]), "+f"(c[2]), "+f"(c[3])
      : "r"(a[0]), "r"(a[1]), "r"(a[2]), "r"(a[3]), "r"(b0), "r"(b1));
}
__device__ __forceinline__ uint32_t swz(uint32_t off) {   // 128B-row swizzle
  return off ^ (((off >> 7) & 7u) << 4);
}
__device__ __forceinline__ uint32_t swz64(uint32_t off) { // 64B-row swizzle
  return off ^ (((off >> 7) & 3u) << 4);
}
__device__ __forceinline__ uint32_t packh2(float a, float b) {
  __half2 h = __floats2half2_rn(a, b);
  return *(uint32_t*)&h;
}
__device__ __forceinline__ float ex2f(float x) {
  float r;
  asm("ex2.approx.f32 %0, %1;" : "=f"(r) : "f"(x));
  return r;
}
__device__ __forceinline__ void cp16(uint32_t dst, const void* src) {
  asm volatile("cp.async.cg.shared.global [%0], [%1], 16;" :: "r"(dst), "l"(src) : "memory");
}
#define CP_COMMIT() asm volatile("cp.async.commit_group;" ::: "memory")
#define CP_WAIT0()  asm volatile("cp.async.wait_group 0;" ::: "memory")

// ---------------------------------------------------------------------------
// Kernel 0: transpose W to [n=192][k=1024] fp16 via coalesced smem tiles.
// ---------------------------------------------------------------------------
__global__ void wprep_kernel(const float* __restrict__ Wq,
                             const float* __restrict__ Wk,
                             const float* __restrict__ Wv) {
  __shared__ float tile[32][33];
  const int bk   = blockIdx.x & 31;
  const int rest = blockIdx.x >> 5;
  const int m    = rest >> 1;
  const int h0   = (rest & 1) * 32;
  const float* W = (m == 0) ? Wq : (m == 1) ? Wk : Wv;
  const int tx = threadIdx.x & 31, ty = threadIdx.x >> 5;
  const int k0 = bk * 32;

#pragma unroll
  for (int j = 0; j < 32; j += 8)
    tile[ty + j][tx] = W[(size_t)(k0 + ty + j) * HH + h0 + tx];
  __syncthreads();
#pragma unroll
  for (int j = 0; j < 32; j += 8)
    g_wt16[(size_t)(m * 64 + h0 + ty + j) * CC + k0 + tx] =
        __float2half_rn(tile[tx][ty + j]);
}

// ---------------------------------------------------------------------------
// Kernel 1 v6 (fixed): QKV projection, fp16, 2 CTA/SM (single wave).
// Stage (38KB): A fp16 @0 (8KB), B fp16 @8192 (12KB), X fp32 @20480 (18KB,
// 144B row stride). x staged via cp.async; converted smem->smem (8 floats/thr).
// ---------------------------------------------------------------------------
#define SA 0u
#define SBOFF 8192u
#define SX 20480u
#define PSTG 38912u
#define PROJ_SMEM (2 * 38912)

__device__ __forceinline__ void proj_issue(uint32_t sb, int tid, int c,
                                           const float* x, int blk) {
  const uint32_t stg = sb + ((uint32_t)c & 1u) * PSTG;
  // B: 768 cp16 (192 rows x 4 units)
  {
    int row = tid >> 2, u = tid & 3;
    cp16(stg + SBOFF + swz64((uint32_t)row * 64 + (uint32_t)u * 16),
         g_wt16 + (size_t)row * CC + c * 32 + u * 8);
  }
  if (tid < 256) {
    int idx = tid + 512;
    int row = idx >> 2, u = idx & 3;
    cp16(stg + SBOFF + swz64((uint32_t)row * 64 + (uint32_t)u * 16),
         g_wt16 + (size_t)row * CC + c * 32 + u * 8);
  }
  // X: 1024 cp16 (128 rows x 8 segs of the fp32 chunk)
#pragma unroll
  for (int i = 0; i < 2; i++) {
    int idx = tid + 512 * i;
    int row = idx >> 3, seg = idx & 7;
    cp16(stg + SX + (uint32_t)row * 144 + (uint32_t)seg * 16,
         x + (size_t)(blk + row) * CC + c * 32 + seg * 4);
  }
  CP_COMMIT();
}

__global__ __launch_bounds__(512, 2) void qkv_mma_kernel(const float* __restrict__ x) {
  extern __shared__ char sm[];
  const uint32_t sb = smem_u32(sm);
  const int tid  = threadIdx.x;
  const int lane = tid & 31;
  const int wid  = tid >> 5;
  const int wm   = wid & 3;
  const int wn   = wid >> 2;
  const int blk  = blockIdx.x * 128;

  float acc[2][6][4];
#pragma unroll
  for (int mi = 0; mi < 2; mi++)
#pragma unroll
    for (int ni = 0; ni < 6; ni++)
#pragma unroll
      for (int j = 0; j < 4; j++) acc[mi][ni][j] = 0.0f;

  const int ar = tid >> 2;          // convert: row 0..127
  const int q4 = tid & 3;           // convert: 8-float quarter of the 32-float row

  const int rowA0 = wm * 32 + ((lane >> 3) & 1) * 8 + (lane & 7);
  const uint32_t koffA = ((lane >> 4) & 1) * 16;
  const int rowB0 = wn * 48 + ((lane >> 4) & 1) * 8 + (lane & 7);
  const uint32_t koffB = ((lane >> 3) & 1) * 16;

  proj_issue(sb, tid, 0, x, blk);

#pragma unroll 1
  for (int c = 0; c < 32; c++) {
    CP_WAIT0();
    __syncthreads();   // B[c],X[c] published; prev-stage readers done

    if (c < 31) proj_issue(sb, tid, c + 1, x, blk);

    // ---- convert X[c] (fp32 smem) -> A[c] (fp16 smem), 8 floats/thread ----
    {
      const uint32_t so = ((uint32_t)c & 1u) * PSTG;
      const char* xs = sm + so + SX + (uint32_t)ar * 144 + (uint32_t)q4 * 32;
      float4 f0 = *(const float4*)(xs);
      float4 f1 = *(const float4*)(xs + 16);
      uint4 h = make_uint4(packh2(f0.x, f0.y), packh2(f0.z, f0.w),
                           packh2(f1.x, f1.y), packh2(f1.z, f1.w));
      *(uint4*)(sm + so + SA + swz64((uint32_t)ar * 64 + (uint32_t)q4 * 16)) = h;
    }
    __syncthreads();   // A[c] visible

    // ---- compute chunk c: 24 MMA/warp ----
    const uint32_t stage = sb + ((uint32_t)c & 1u) * PSTG;
#pragma unroll
    for (int kk = 0; kk < 2; kk++) {
      uint32_t aF[2][4];
#pragma unroll
      for (int mi = 0; mi < 2; mi++) {
        uint32_t sw = swz64((uint32_t)(rowA0 + 16 * mi) * 64 + kk * 32 + koffA);
        ldsm_x4(aF[mi], stage + SA + sw);
      }
#pragma unroll
      for (int pi = 0; pi < 3; pi++) {
        uint32_t bF[4];
        uint32_t sw = swz64((uint32_t)(rowB0 + 16 * pi) * 64 + kk * 32 + koffB);
        ldsm_x4(bF, stage + SBOFF + sw);
#pragma unroll
        for (int mi = 0; mi < 2; mi++) {
#pragma unroll
          for (int h = 0; h < 2; h++)
            mma_f16(acc[mi][2 * pi + h], aF[mi], bF[2 * h], bF[2 * h + 1]);
        }
      }
    }
  }

  // ---- epilogue: q,k,v single fp16 packed ----
  const int g = lane >> 2, t = lane & 3;
#pragma unroll
  for (int mi = 0; mi < 2; mi++) {
#pragma unroll
    for (int ni = 0; ni < 6; ni++) {
      int col = wn * 48 + ni * 8 + t * 2;
#pragma unroll
      for (int half = 0; half < 2; half++) {
        int row = blk + wm * 32 + mi * 16 + g + half * 8;
        float a = acc[mi][ni][2 * half], b = acc[mi][ni][2 * half + 1];
        g_qkv32[(size_t)row * 96 + (col >> 1)] = packh2(a, b);
      }
    }
  }
}

// ---------------------------------------------------------------------------
// Kernel 2 v8: FA2 attention fp16, KTILE=128, diag-half skip, Q in registers,
// grid 512 LPT. smem: Q 8KB @0; 2 stages of 32KB @8192. 72KB.
// ---------------------------------------------------------------------------
#define QS 0
#define ST0 8192
#define STG_SZ 32768
#define OBUF 0
#define LBUF 16384
#define ATT_SMEM (8192 + 2 * 32768)  // 72 KB

__global__ __launch_bounds__(256, 2) void attn8_kernel(float* __restrict__ out) {
  extern __shared__ char sm[];
  const uint32_t sb = smem_u32(sm);
  const int b    = blockIdx.x & 15;
  const int qt   = 31 - (blockIdx.x >> 4);  // heaviest first
  const int tid  = threadIdx.x;
  const int lane = tid & 31;
  const int wid  = tid >> 5;
  const int wm   = wid & 3;
  const int wn   = wid >> 2;   // key half: wn*64
  const int g    = lane >> 2;
  const int t    = lane & 3;
  const float scale2 = 0.03125f * 1.44269504f;
  const int KC = (qt + 2) >> 1;  // number of 128-key chunks

  const uint32_t relA_base = (uint32_t)(wm * 16 + ((lane >> 3) & 1) * 8 + (lane & 7)) * 128 +
                             ((lane >> 4) & 1) * 16;
  const uint32_t rowB_l = (uint32_t)(((lane >> 4) & 1) * 8 + (lane & 7));
  const uint32_t koffB  = ((lane >> 3) & 1) * 16;
  const uint32_t rowV_l = (uint32_t)(lane & 15);
  const uint32_t doffV  = ((lane >> 4) & 1) * 8;
  const int qr0 = qt * 64 + wm * 16 + g;

  // ---- prologue: Q + chunk 0 ----
#pragma unroll
  for (int it = 0; it < 2; it++) {
    int idx = tid + 256 * it;
    int row = idx >> 3, seg = idx & 7;
    cp16(sb + QS + swz((uint32_t)row * 128 + seg * 16),
         g_qkv32 + ((size_t)b * TT + qt * 64 + row) * 96 + seg * 4);
  }
  const int pr = tid >> 3, pseg = tid & 7;
  uint32_t dA[4];
#pragma unroll
  for (int i = 0; i < 4; i++)
    dA[i] = swz((uint32_t)(pr + 32 * i) * 128 + pseg * 16);
  const char* pf = (const char*)(g_qkv32 + ((size_t)b * TT + pr) * 96 + 32 + pseg * 4);
  {
    const uint32_t s0 = sb + ST0;
#pragma unroll
    for (int i = 0; i < 4; i++) {
      cp16(s0 + dA[i],          pf + i * 12288);        // K rows
      cp16(s0 + 16384u + dA[i], pf + i * 12288 + 128);  // V rows
    }
  }
  CP_COMMIT();
  CP_WAIT0();
  __syncthreads();

  uint32_t qF[4][4];
#pragma unroll
  for (int kk = 0; kk < 4; kk++)
    ldsm_x4(qF[kk], sb + QS + swz(relA_base + kk * 32));

  pf += 49152;  // next chunk source

  float o[8][4];
#pragma unroll
  for (int nb = 0; nb < 8; nb++)
#pragma unroll
    for (int j = 0; j < 4; j++) o[nb][j] = 0.0f;
  float lsum0 = 0.0f, lsum1 = 0.0f;

#pragma unroll 1
  for (int c = 0; c < KC; c++) {
    const bool more = (c + 1 < KC);
    if (more) {
      const uint32_t s2 = sb + ST0 + (uint32_t)((c + 1) & 1) * STG_SZ;
#pragma unroll
      for (int i = 0; i < 4; i++) {
        cp16(s2 + dA[i],          pf + i * 12288);
        cp16(s2 + 16384u + dA[i], pf + i * 12288 + 128);
      }
      CP_COMMIT();
      pf += 49152;
    }

    const bool last = (c == KC - 1);
    const bool skip = last && !(qt & 1) && (wn == 1);  // fully-masked half
    if (!skip) {
      const uint32_t Kb = sb + ST0 + (uint32_t)(c & 1) * STG_SZ;
      const uint32_t Vb = Kb + 16384u;

      // ---- Phase A: S = Q K^T over 64 keys ----
      float sA[8][4];
#pragma unroll
      for (int nb = 0; nb < 8; nb++)
#pragma unroll
        for (int j = 0; j < 4; j++) sA[nb][j] = 0.0f;

#pragma unroll
      for (int kk = 0; kk < 4; kk++) {
#pragma unroll
        for (int nb2 = 0; nb2 < 4; nb2++) {
          uint32_t bF[4];
          uint32_t relB = swz((uint32_t)(wn * 64 + nb2 * 16 + rowB_l) * 128 +
                              kk * 32 + koffB);
          ldsm_x4(bF, Kb + relB);
#pragma unroll
          for (int h = 0; h < 2; h++)
            mma_f16(sA[2 * nb2 + h], qF[kk], bF[2 * h], bF[2 * h + 1]);
        }
      }

      // ---- exp2 + causal mask + rowsum ----
      const int keybase = c * 128 + wn * 64;
#pragma unroll
      for (int nb = 0; nb < 8; nb++) {
#pragma unroll
        for (int j = 0; j < 4; j++) {
          float e = ex2f(sA[nb][j] * scale2);
          if (last) {
            int key = keybase + nb * 8 + t * 2 + (j & 1);
            int qr  = qr0 + ((j >> 1) << 3);
            if (key > qr) e = 0.0f;
          }
          sA[nb][j] = e;
          if (j < 2) lsum0 += e; else lsum1 += e;
        }
      }

      // ---- Phase B: O += P V ----
#pragma unroll
      for (int kb = 0; kb < 4; kb++) {
        uint32_t pF[4];
        pF[0] = packh2(sA[2 * kb][0],     sA[2 * kb][1]);
        pF[1] = packh2(sA[2 * kb][2],     sA[2 * kb][3]);
        pF[2] = packh2(sA[2 * kb + 1][0], sA[2 * kb + 1][1]);
        pF[3] = packh2(sA[2 * kb + 1][2], sA[2 * kb + 1][3]);
#pragma unroll
        for (int dg = 0; dg < 4; dg++) {
          uint32_t vF[4];
          uint32_t relV = swz((uint32_t)(wn * 64 + kb * 16 + rowV_l) * 128 +
                              (dg * 16 + doffV) * 2);
          ldsm_x4_t(vF, Vb + relV);
#pragma unroll
          for (int h = 0; h < 2; h++)
            mma_f16(o[dg * 2 + h], pF, vF[2 * h], vF[2 * h + 1]);
        }
      }
    }

    if (more) {
      CP_WAIT0();
      __syncthreads();
    }
  }

  // ---- epilogue: combine key-halves, normalize, store ----
  lsum0 += __shfl_xor_sync(0xffffffffu, lsum0, 1);
  lsum0 += __shfl_xor_sync(0xffffffffu, lsum0, 2);
  lsum1 += __shfl_xor_sync(0xffffffffu, lsum1, 1);
  lsum1 += __shfl_xor_sync(0xffffffffu, lsum1, 2);

  __syncthreads();
  float* obuf = (float*)(sm + OBUF) + wm * 1024;
  float* lbuf = (float*)(sm + LBUF) + wm * 16;
  if (wn == 1) {
#pragma unroll
    for (int nb = 0; nb < 8; nb++) {
      int col = nb * 8 + t * 2;
      *(float2*)(obuf + g * 64 + col)       = make_float2(o[nb][0], o[nb][1]);
      *(float2*)(obuf + (g + 8) * 64 + col) = make_float2(o[nb][2], o[nb][3]);
    }
    if (t == 0) { lbuf[g] = lsum0; lbuf[g + 8] = lsum1; }
  }
  __syncthreads();
  if (wn == 0) {
    float inv0 = 1.0f / (lsum0 + lbuf[g]);
    float inv1 = 1.0f / (lsum1 + lbuf[g + 8]);
    size_t r0 = ((size_t)b * TT + qt * 64 + wm * 16 + g) * HH;
    size_t r1 = r0 + 8 * HH;
#pragma unroll
    for (int nb = 0; nb < 8; nb++) {
      int col = nb * 8 + t * 2;
      float2 pa = *(float2*)(obuf + g * 64 + col);
      float2 pb = *(float2*)(obuf + (g + 8) * 64 + col);
      *(float2*)(out + r0 + col) =
          make_float2((o[nb][0] + pa.x) * inv0, (o[nb][1] + pa.y) * inv0);
      *(float2*)(out + r1 + col) =
          make_float2((o[nb][2] + pb.x) * inv1, (o[nb][3] + pb.y) * inv1);
    }
  }
}

// ---------------------------------------------------------------------------
extern "C" void kernel_launch(void* const* d_in, const int* in_sizes, int n_in,
                              void* d_out, int out_size) {
  const float* x  = (const float*)d_in[0];
  const float* Wq = (const float*)d_in[1];
  const float* Wk = (const float*)d_in[2];
  const float* Wv = (const float*)d_in[3];
  float* out = (float*)d_out;

  cudaFuncSetAttribute(qkv_mma_kernel, cudaFuncAttributeMaxDynamicSharedMemorySize, PROJ_SMEM);
  cudaFuncSetAttribute(attn8_kernel, cudaFuncAttributeMaxDynamicSharedMemorySize, ATT_SMEM);

  wprep_kernel<<<192, 256>>>(Wq, Wk, Wv);
  qkv_mma_kernel<<<NROWS / 128, 512, PROJ_SMEM>>>(x);
  attn8_kernel<<<16 * 32, 256, ATT_SMEM>>>(out);
}

// round 15
// speedup vs baseline: 1.0437x; 1.0437x over previous
#include <cuda_runtime.h>
#include <cuda_fp16.h>
#include <cstdint>

#define BB 16
#define TT 2048
#define CC 1024
#define HH 64
#define NROWS (BB * TT)

// QKV scratch, single fp16, packed 2 per uint32: [B*T][96] uint32
//   q: cols 0..31, k: 32..63, v: 64..95
__device__ uint32_t g_qkv32[(size_t)NROWS * 96];
// W transposed, single fp16: [192][1024]
__device__ __half g_wt16[192 * CC];

// ---------------------------------------------------------------------------
// helpers (sm_80+ baseline ISA)
// ---------------------------------------------------------------------------
__device__ __forceinline__ uint32_t smem_u32(const void* p) {
  return (uint32_t)__cvta_generic_to_shared(p);
}
__device__ __forceinline__ void ldsm_x4(uint32_t* r, uint32_t addr) {
  asm volatile("ldmatrix.sync.aligned.m8n8.x4.shared.b16 {%0,%1,%2,%3}, [%4];"
               : "=r"(r[0]), "=r"(r[1]), "=r"(r[2]), "=r"(r[3]) : "r"(addr));
}
__device__ __forceinline__ void ldsm_x4_t(uint32_t* r, uint32_t addr) {
  asm volatile("ldmatrix.sync.aligned.m8n8.x4.trans.shared.b16 {%0,%1,%2,%3}, [%4];"
               : "=r"(r[0]), "=r"(r[1]), "=r"(r[2]), "=r"(r[3]) : "r"(addr));
}
__device__ __forceinline__ void mma_f16(float* c, const uint32_t* a,
                                        uint32_t b0, uint32_t b1) {
  asm volatile(
      "mma.sync.aligned.m16n8k16.row.col.f32.f16.f16.f32 "
      "{%0,%1,%2,%3}, {%4,%5,%6,%7}, {%8,%9}, {%0,%1,%2,%3};"
      : "+f"(c[0]), "+f"(c[1]), "+f"(c[2]), "+f"(c[3])
      : "r"(a[0]), "r"(a[1]), "r"(a[2]), "r"(a[3]), "r"(b0), "r"(b1));
}
__device__ __forceinline__ uint32_t swz(uint32_t off) {   // 128B-row swizzle
  return off ^ (((off >> 7) & 7u) << 4);
}
__device__ __forceinline__ uint32_t swz64(uint32_t off) { // 64B-row swizzle
  return off ^ (((off >> 7) & 3u) << 4);
}
__device__ __forceinline__ uint32_t packh2(float a, float b) {
  __half2 h = __floats2half2_rn(a, b);
  return *(uint32_t*)&h;
}
__device__ __forceinline__ float ex2f(float x) {
  float r;
  asm("ex2.approx.f32 %0, %1;" : "=f"(r) : "f"(x));
  return r;
}
__device__ __forceinline__ void cp16(uint32_t dst, const void* src) {
  asm volatile("cp.async.cg.shared.global [%0], [%1], 16;" :: "r"(dst), "l"(src) : "memory");
}
#define CP_COMMIT() asm volatile("cp.async.commit_group;" ::: "memory")
#define CP_WAIT0()  asm volatile("cp.async.wait_group 0;" ::: "memory")

// ---------------------------------------------------------------------------
// Kernel 0: transpose W to [n=192][k=1024] fp16 via coalesced smem tiles.
// ---------------------------------------------------------------------------
__global__ void wprep_kernel(const float* __restrict__ Wq,
                             const float* __restrict__ Wk,
                             const float* __restrict__ Wv) {
  __shared__ float tile[32][33];
  const int bk   = blockIdx.x & 31;
  const int rest = blockIdx.x >> 5;
  const int m    = rest >> 1;
  const int h0   = (rest & 1) * 32;
  const float* W = (m == 0) ? Wq : (m == 1) ? Wk : Wv;
  const int tx = threadIdx.x & 31, ty = threadIdx.x >> 5;
  const int k0 = bk * 32;

#pragma unroll
  for (int j = 0; j < 32; j += 8)
    tile[ty + j][tx] = W[(size_t)(k0 + ty + j) * HH + h0 + tx];
  __syncthreads();
#pragma unroll
  for (int j = 0; j < 32; j += 8)
    g_wt16[(size_t)(m * 64 + h0 + ty + j) * CC + k0 + tx] =
        __float2half_rn(tile[tx][ty + j]);
}

// ---------------------------------------------------------------------------
// Kernel 1 v6: QKV projection, fp16, 2 CTA/SM (single wave).
// Stage (38KB): A fp16 @0 (8KB), B fp16 @8192 (12KB), X fp32 @20480 (18KB,
// 144B row stride). x staged via cp.async; converted smem->smem (8 floats/thr).
// ---------------------------------------------------------------------------
#define SA 0u
#define SBOFF 8192u
#define SX 20480u
#define PSTG 38912u
#define PROJ_SMEM (2 * 38912)

__device__ __forceinline__ void proj_issue(uint32_t sb, int tid, int c,
                                           const float* x, int blk) {
  const uint32_t stg = sb + ((uint32_t)c & 1u) * PSTG;
  {
    int row = tid >> 2, u = tid & 3;
    cp16(stg + SBOFF + swz64((uint32_t)row * 64 + (uint32_t)u * 16),
         g_wt16 + (size_t)row * CC + c * 32 + u * 8);
  }
  if (tid < 256) {
    int idx = tid + 512;
    int row = idx >> 2, u = idx & 3;
    cp16(stg + SBOFF + swz64((uint32_t)row * 64 + (uint32_t)u * 16),
         g_wt16 + (size_t)row * CC + c * 32 + u * 8);
  }
#pragma unroll
  for (int i = 0; i < 2; i++) {
    int idx = tid + 512 * i;
    int row = idx >> 3, seg = idx & 7;
    cp16(stg + SX + (uint32_t)row * 144 + (uint32_t)seg * 16,
         x + (size_t)(blk + row) * CC + c * 32 + seg * 4);
  }
  CP_COMMIT();
}

__global__ __launch_bounds__(512, 2) void qkv_mma_kernel(const float* __restrict__ x) {
  extern __shared__ char sm[];
  const uint32_t sb = smem_u32(sm);
  const int tid  = threadIdx.x;
  const int lane = tid & 31;
  const int wid  = tid >> 5;
  const int wm   = wid & 3;
  const int wn   = wid >> 2;
  const int blk  = blockIdx.x * 128;

  float acc[2][6][4];
#pragma unroll
  for (int mi = 0; mi < 2; mi++)
#pragma unroll
    for (int ni = 0; ni < 6; ni++)
#pragma unroll
      for (int j = 0; j < 4; j++) acc[mi][ni][j] = 0.0f;

  const int ar = tid >> 2;
  const int q4 = tid & 3;

  const int rowA0 = wm * 32 + ((lane >> 3) & 1) * 8 + (lane & 7);
  const uint32_t koffA = ((lane >> 4) & 1) * 16;
  const int rowB0 = wn * 48 + ((lane >> 4) & 1) * 8 + (lane & 7);
  const uint32_t koffB = ((lane >> 3) & 1) * 16;

  proj_issue(sb, tid, 0, x, blk);

#pragma unroll 1
  for (int c = 0; c < 32; c++) {
    CP_WAIT0();
    __syncthreads();

    if (c < 31) proj_issue(sb, tid, c + 1, x, blk);

    // ---- convert X[c] (fp32 smem) -> A[c] (fp16 smem), 8 floats/thread ----
    {
      const uint32_t so = ((uint32_t)c & 1u) * PSTG;
      const char* xs = sm + so + SX + (uint32_t)ar * 144 + (uint32_t)q4 * 32;
      float4 f0 = *(const float4*)(xs);
      float4 f1 = *(const float4*)(xs + 16);
      uint4 h = make_uint4(packh2(f0.x, f0.y), packh2(f0.z, f0.w),
                           packh2(f1.x, f1.y), packh2(f1.z, f1.w));
      *(uint4*)(sm + so + SA + swz64((uint32_t)ar * 64 + (uint32_t)q4 * 16)) = h;
    }
    __syncthreads();

    const uint32_t stage = sb + ((uint32_t)c & 1u) * PSTG;
#pragma unroll
    for (int kk = 0; kk < 2; kk++) {
      uint32_t aF[2][4];
#pragma unroll
      for (int mi = 0; mi < 2; mi++) {
        uint32_t sw = swz64((uint32_t)(rowA0 + 16 * mi) * 64 + kk * 32 + koffA);
        ldsm_x4(aF[mi], stage + SA + sw);
      }
#pragma unroll
      for (int pi = 0; pi < 3; pi++) {
        uint32_t bF[4];
        uint32_t sw = swz64((uint32_t)(rowB0 + 16 * pi) * 64 + kk * 32 + koffB);
        ldsm_x4(bF, stage + SBOFF + sw);
#pragma unroll
        for (int mi = 0; mi < 2; mi++) {
#pragma unroll
          for (int h = 0; h < 2; h++)
            mma_f16(acc[mi][2 * pi + h], aF[mi], bF[2 * h], bF[2 * h + 1]);
        }
      }
    }
  }

  const int g = lane >> 2, t = lane & 3;
#pragma unroll
  for (int mi = 0; mi < 2; mi++) {
#pragma unroll
    for (int ni = 0; ni < 6; ni++) {
      int col = wn * 48 + ni * 8 + t * 2;
#pragma unroll
      for (int half = 0; half < 2; half++) {
        int row = blk + wm * 32 + mi * 16 + g + half * 8;
        float a = acc[mi][ni][2 * half], b = acc[mi][ni][2 * half + 1];
        g_qkv32[(size_t)row * 96 + (col >> 1)] = packh2(a, b);
      }
    }
  }
}

// ---------------------------------------------------------------------------
// Kernel 2 v7 (R12, known good): FA2 attention fp16, KTILE=64, grid 512 LPT,
// Q fragments in registers, strength-reduced prefetch, ex2 softmax.
// ---------------------------------------------------------------------------
#define QS 0
#define ST0 8192
#define STAGE_SZ 16384           // K@+0, V@+8192
#define OBUF 0
#define LBUF 16384
#define ATT_SMEM (8192 + 2 * 16384)  // 40 KB

__global__ __launch_bounds__(256, 2) void attn7_kernel(float* __restrict__ out) {
  extern __shared__ char sm[];
  const uint32_t sb = smem_u32(sm);
  const int b    = blockIdx.x & 15;
  const int qt   = 31 - (blockIdx.x >> 4);
  const int tid  = threadIdx.x;
  const int lane = tid & 31;
  const int wid  = tid >> 5;
  const int wm   = wid & 3;
  const int wn   = wid >> 2;
  const int g    = lane >> 2;
  const int t    = lane & 3;
  const float scale2 = 0.03125f * 1.44269504f;

  const uint32_t relA_base = (uint32_t)(wm * 16 + ((lane >> 3) & 1) * 8 + (lane & 7)) * 128 +
                             ((lane >> 4) & 1) * 16;
  const uint32_t rowB_l = (uint32_t)(((lane >> 4) & 1) * 8 + (lane & 7));
  const uint32_t koffB  = ((lane >> 3) & 1) * 16;
  const uint32_t rowV_l = (uint32_t)(lane & 15);
  const uint32_t doffV  = ((lane >> 4) & 1) * 8;

#pragma unroll
  for (int it = 0; it < 2; it++) {
    int idx = tid + 256 * it;
    int row = idx >> 3;
    int seg = idx & 7;
    const void* src = g_qkv32 + ((size_t)b * TT + qt * 64 + row) * 96 + seg * 4;
    cp16(sb + QS + swz((uint32_t)row * 128 + seg * 16), src);
  }
  const int pr  = tid >> 3;
  const int pseg = tid & 7;
  const uint32_t d0 = swz((uint32_t)pr * 128 + pseg * 16);
  const uint32_t d1 = swz((uint32_t)(pr + 32) * 128 + pseg * 16);
  const char* pf0 = (const char*)(g_qkv32 + ((size_t)b * TT + pr) * 96 + 32 + pseg * 4);
  {
    cp16(sb + ST0 + d0,         pf0);
    cp16(sb + ST0 + d1,         pf0 + 12288);
    cp16(sb + ST0 + 8192u + d0, pf0 + 128);
    cp16(sb + ST0 + 8192u + d1, pf0 + 12288 + 128);
  }
  CP_COMMIT();
  CP_WAIT0();
  __syncthreads();

  uint32_t qF[4][4];
#pragma unroll
  for (int kk = 0; kk < 4; kk++)
    ldsm_x4(qF[kk], sb + QS + swz(relA_base + kk * 32));

  const char* pf = pf0 + 24576;

  float o[8][4];
#pragma unroll
  for (int nb = 0; nb < 8; nb++)
#pragma unroll
    for (int j = 0; j < 4; j++) o[nb][j] = 0.0f;
  float lsum0 = 0.0f, lsum1 = 0.0f;

#pragma unroll 1
  for (int kt = 0; kt <= qt; kt++) {
    const bool more = (kt < qt);
    if (more) {
      const uint32_t stb2 = sb + ST0 + (uint32_t)((kt + 1) & 1) * STAGE_SZ;
      cp16(stb2 + d0,         pf);
      cp16(stb2 + d1,         pf + 12288);
      cp16(stb2 + 8192u + d0, pf + 128);
      cp16(stb2 + 8192u + d1, pf + 12288 + 128);
      CP_COMMIT();
      pf += 24576;
    }

    const uint32_t stb = sb + ST0 + (uint32_t)(kt & 1) * STAGE_SZ;
    const uint32_t Ko = stb, Vo = stb + 8192u;

    float sA[4][4];
#pragma unroll
    for (int nb = 0; nb < 4; nb++)
#pragma unroll
      for (int j = 0; j < 4; j++) sA[nb][j] = 0.0f;

#pragma unroll
    for (int kk = 0; kk < 4; kk++) {
#pragma unroll
      for (int nb2 = 0; nb2 < 2; nb2++) {
        uint32_t bF[4];
        uint32_t relB = swz((uint32_t)(wn * 32 + nb2 * 16 + rowB_l) * 128 + kk * 32 + koffB);
        ldsm_x4(bF, Ko + relB);
#pragma unroll
        for (int h = 0; h < 2; h++)
          mma_f16(sA[2 * nb2 + h], qF[kk], bF[2 * h], bF[2 * h + 1]);
      }
    }

    const bool diag = (kt == qt);
#pragma unroll
    for (int nb = 0; nb < 4; nb++) {
#pragma unroll
      for (int j = 0; j < 4; j++) {
        float e = ex2f(sA[nb][j] * scale2);
        if (diag) {
          int row = wm * 16 + g + ((j >= 2) ? 8 : 0);
          int col = wn * 32 + nb * 8 + t * 2 + (j & 1);
          if (col > row) e = 0.0f;
        }
        sA[nb][j] = e;
        if (j < 2) lsum0 += e; else lsum1 += e;
      }
    }

#pragma unroll
    for (int kb = 0; kb < 2; kb++) {
      uint32_t pF[4];
      pF[0] = packh2(sA[2 * kb][0],     sA[2 * kb][1]);
      pF[1] = packh2(sA[2 * kb][2],     sA[2 * kb][3]);
      pF[2] = packh2(sA[2 * kb + 1][0], sA[2 * kb + 1][1]);
      pF[3] = packh2(sA[2 * kb + 1][2], sA[2 * kb + 1][3]);
#pragma unroll
      for (int dg = 0; dg < 4; dg++) {
        uint32_t vF[4];
        uint32_t relV = swz((uint32_t)(wn * 32 + kb * 16 + rowV_l) * 128 +
                            (dg * 16 + doffV) * 2);
        ldsm_x4_t(vF, Vo + relV);
#pragma unroll
        for (int h = 0; h < 2; h++)
          mma_f16(o[dg * 2 + h], pF, vF[2 * h], vF[2 * h + 1]);
      }
    }

    if (more) {
      CP_WAIT0();
      __syncthreads();
    }
  }

  lsum0 += __shfl_xor_sync(0xffffffffu, lsum0, 1);
  lsum0 += __shfl_xor_sync(0xffffffffu, lsum0, 2);
  lsum1 += __shfl_xor_sync(0xffffffffu, lsum1, 1);
  lsum1 += __shfl_xor_sync(0xffffffffu, lsum1, 2);

  __syncthreads();
  float* obuf = (float*)(sm + OBUF) + wm * 1024;
  float* lbuf = (float*)(sm + LBUF) + wm * 16;
  if (wn == 1) {
#pragma unroll
    for (int nb = 0; nb < 8; nb++) {
      int col = nb * 8 + t * 2;
      *(float2*)(obuf + g * 64 + col)       = make_float2(o[nb][0], o[nb][1]);
      *(float2*)(obuf + (g + 8) * 64 + col) = make_float2(o[nb][2], o[nb][3]);
    }
    if (t == 0) { lbuf[g] = lsum0; lbuf[g + 8] = lsum1; }
  }
  __syncthreads();
  if (wn == 0) {
    float inv0 = 1.0f / (lsum0 + lbuf[g]);
    float inv1 = 1.0f / (lsum1 + lbuf[g + 8]);
    size_t r0 = ((size_t)b * TT + qt * 64 + wm * 16 + g) * HH;
    size_t r1 = r0 + 8 * HH;
#pragma unroll
    for (int nb = 0; nb < 8; nb++) {
      int col = nb * 8 + t * 2;
      float2 pa = *(float2*)(obuf + g * 64 + col);
      float2 pb = *(float2*)(obuf + (g + 8) * 64 + col);
      *(float2*)(out + r0 + col) =
          make_float2((o[nb][0] + pa.x) * inv0, (o[nb][1] + pa.y) * inv0);
      *(float2*)(out + r1 + col) =
          make_float2((o[nb][2] + pb.x) * inv1, (o[nb][3] + pb.y) * inv1);
    }
  }
}

// ---------------------------------------------------------------------------
extern "C" void kernel_launch(void* const* d_in, const int* in_sizes, int n_in,
                              void* d_out, int out_size) {
  const float* x  = (const float*)d_in[0];
  const float* Wq = (const float*)d_in[1];
  const float* Wk = (const float*)d_in[2];
  const float* Wv = (const float*)d_in[3];
  float* out = (float*)d_out;

  cudaFuncSetAttribute(qkv_mma_kernel, cudaFuncAttributeMaxDynamicSharedMemorySize, PROJ_SMEM);
  cudaFuncSetAttribute(attn7_kernel, cudaFuncAttributeMaxDynamicSharedMemorySize, ATT_SMEM);

  wprep_kernel<<<192, 256>>>(Wq, Wk, Wv);
  qkv_mma_kernel<<<NROWS / 128, 512, PROJ_SMEM>>>(x);
  attn7_kernel<<<16 * 32, 256, ATT_SMEM>>>(out);
}

// round 16
// speedup vs baseline: 1.2335x; 1.1819x over previous
#include <cuda_runtime.h>
#include <cuda_fp16.h>
#include <cstdint>

#define BB 16
#define TT 2048
#define CC 1024
#define HH 64
#define NROWS (BB * TT)

// QKV scratch, single fp16, packed 2 per uint32: [B*T][96] uint32
//   q: cols 0..31, k: 32..63, v: 64..95
__device__ uint32_t g_qkv32[(size_t)NROWS * 96];
// W transposed, single fp16: [192][1024]
__device__ __half g_wt16[192 * CC];

// ---------------------------------------------------------------------------
// helpers (sm_80+ baseline ISA)
// ---------------------------------------------------------------------------
__device__ __forceinline__ uint32_t smem_u32(const void* p) {
  return (uint32_t)__cvta_generic_to_shared(p);
}
__device__ __forceinline__ void ldsm_x4(uint32_t* r, uint32_t addr) {
  asm volatile("ldmatrix.sync.aligned.m8n8.x4.shared.b16 {%0,%1,%2,%3}, [%4];"
               : "=r"(r[0]), "=r"(r[1]), "=r"(r[2]), "=r"(r[3]) : "r"(addr));
}
__device__ __forceinline__ void ldsm_x4_t(uint32_t* r, uint32_t addr) {
  asm volatile("ldmatrix.sync.aligned.m8n8.x4.trans.shared.b16 {%0,%1,%2,%3}, [%4];"
               : "=r"(r[0]), "=r"(r[1]), "=r"(r[2]), "=r"(r[3]) : "r"(addr));
}
__device__ __forceinline__ void mma_f16(float* c, const uint32_t* a,
                                        uint32_t b0, uint32_t b1) {
  asm volatile(
      "mma.sync.aligned.m16n8k16.row.col.f32.f16.f16.f32 "
      "{%0,%1,%2,%3}, {%4,%5,%6,%7}, {%8,%9}, {%0,%1,%2,%3};"
      : "+f"(c[0]), "+f"(c[1]), "+f"(c[2]), "+f"(c[3])
      : "r"(a[0]), "r"(a[1]), "r"(a[2]), "r"(a[3]), "r"(b0), "r"(b1));
}
__device__ __forceinline__ uint32_t swz(uint32_t off) {   // 128B-row swizzle
  return off ^ (((off >> 7) & 7u) << 4);
}
__device__ __forceinline__ uint32_t swz64(uint32_t off) { // 64B-row swizzle
  return off ^ (((off >> 7) & 3u) << 4);
}
__device__ __forceinline__ uint32_t packh2(float a, float b) {
  __half2 h = __floats2half2_rn(a, b);
  return *(uint32_t*)&h;
}
__device__ __forceinline__ uint32_t ex2h2(uint32_t x) {
  uint32_t r;
  asm("ex2.approx.f16x2 %0, %1;" : "=r"(r) : "r"(x));
  return r;
}
__device__ __forceinline__ void cp16(uint32_t dst, const void* src) {
  asm volatile("cp.async.cg.shared.global [%0], [%1], 16;" :: "r"(dst), "l"(src) : "memory");
}
#define CP_COMMIT() asm volatile("cp.async.commit_group;" ::: "memory")
#define CP_WAIT0()  asm volatile("cp.async.wait_group 0;" ::: "memory")

// ---------------------------------------------------------------------------
// Kernel 0: transpose W to [n=192][k=1024] fp16 via coalesced smem tiles.
// ---------------------------------------------------------------------------
__global__ void wprep_kernel(const float* __restrict__ Wq,
                             const float* __restrict__ Wk,
                             const float* __restrict__ Wv) {
  __shared__ float tile[32][33];
  const int bk   = blockIdx.x & 31;
  const int rest = blockIdx.x >> 5;
  const int m    = rest >> 1;
  const int h0   = (rest & 1) * 32;
  const float* W = (m == 0) ? Wq : (m == 1) ? Wk : Wv;
  const int tx = threadIdx.x & 31, ty = threadIdx.x >> 5;
  const int k0 = bk * 32;

#pragma unroll
  for (int j = 0; j < 32; j += 8)
    tile[ty + j][tx] = W[(size_t)(k0 + ty + j) * HH + h0 + tx];
  __syncthreads();
#pragma unroll
  for (int j = 0; j < 32; j += 8)
    g_wt16[(size_t)(m * 64 + h0 + ty + j) * CC + k0 + tx] =
        __float2half_rn(tile[tx][ty + j]);
}

// ---------------------------------------------------------------------------
// Kernel 1 v5 (R12, known good): QKV projection, single fp16.
// 2-stage pipeline, K-chunk 32. Stage (20KB): A@0 (8KB), B@8192 (12KB).
// x loaded direct to registers; 1 sync/chunk; 24 MMA/warp/chunk.
// ---------------------------------------------------------------------------
#define PSTG 20480u
#define PROJ_SMEM (2 * 20480)

__device__ __forceinline__ void proj_issueB(uint32_t sb, int tid, int c) {
  const uint32_t stage = ((uint32_t)c & 1u) * PSTG;
  {
    int row = tid >> 2, u = tid & 3;
    uint32_t sw = swz64((uint32_t)row * 64 + (uint32_t)u * 16);
    cp16(sb + stage + 8192u + sw, g_wt16 + (size_t)row * CC + c * 32 + u * 8);
  }
  if (tid < 256) {
    int idx = tid + 512;
    int row = idx >> 2, u = idx & 3;
    uint32_t sw = swz64((uint32_t)row * 64 + (uint32_t)u * 16);
    cp16(sb + stage + 8192u + sw, g_wt16 + (size_t)row * CC + c * 32 + u * 8);
  }
  CP_COMMIT();
}

__global__ __launch_bounds__(512) void qkv_mma_kernel(const float* __restrict__ x) {
  extern __shared__ char sm[];
  const uint32_t sb = smem_u32(sm);
  const int tid  = threadIdx.x;
  const int lane = tid & 31;
  const int wid  = tid >> 5;
  const int wm   = wid & 3;
  const int wn   = wid >> 2;

  float acc[2][6][4];
#pragma unroll
  for (int mi = 0; mi < 2; mi++)
#pragma unroll
    for (int ni = 0; ni < 6; ni++)
#pragma unroll
      for (int j = 0; j < 4; j++) acc[mi][ni][j] = 0.0f;

  const int ar = tid >> 2;
  const int ac = (tid & 3) * 8;
  const size_t xrow = ((size_t)blockIdx.x * 128 + ar) * CC;
  const uint32_t aoff = swz64((uint32_t)ar * 64 + (uint32_t)(tid & 3) * 16);

  const int rowA0 = wm * 32 + ((lane >> 3) & 1) * 8 + (lane & 7);
  const uint32_t koffA = ((lane >> 4) & 1) * 16;
  const int rowB0 = wn * 48 + ((lane >> 4) & 1) * 8 + (lane & 7);
  const uint32_t koffB = ((lane >> 3) & 1) * 16;

  float4 xv0, xv1;

  proj_issueB(sb, tid, 0);
  xv0 = *(const float4*)(x + xrow + ac);
  xv1 = *(const float4*)(x + xrow + ac + 4);
  {
    uint4 hv = make_uint4(packh2(xv0.x, xv0.y), packh2(xv0.z, xv0.w),
                          packh2(xv1.x, xv1.y), packh2(xv1.z, xv1.w));
    *(uint4*)(sm + aoff) = hv;
  }

#pragma unroll 1
  for (int c = 0; c < 32; c++) {
    CP_WAIT0();
    __syncthreads();

    const bool pf = (c < 31);
    if (pf) {
      proj_issueB(sb, tid, c + 1);
      xv0 = *(const float4*)(x + xrow + (c + 1) * 32 + ac);
      xv1 = *(const float4*)(x + xrow + (c + 1) * 32 + ac + 4);
    }

    const uint32_t stage = sb + ((uint32_t)c & 1u) * PSTG;
#pragma unroll
    for (int kk = 0; kk < 2; kk++) {
      uint32_t aF[2][4];
#pragma unroll
      for (int mi = 0; mi < 2; mi++) {
        uint32_t sw = swz64((uint32_t)(rowA0 + 16 * mi) * 64 + kk * 32 + koffA);
        ldsm_x4(aF[mi], stage + sw);
      }
#pragma unroll
      for (int pi = 0; pi < 3; pi++) {
        uint32_t bF[4];
        uint32_t sw = swz64((uint32_t)(rowB0 + 16 * pi) * 64 + kk * 32 + koffB);
        ldsm_x4(bF, stage + 8192u + sw);
#pragma unroll
        for (int mi = 0; mi < 2; mi++) {
#pragma unroll
          for (int h = 0; h < 2; h++)
            mma_f16(acc[mi][2 * pi + h], aF[mi], bF[2 * h], bF[2 * h + 1]);
        }
      }
    }

    if (pf) {
      uint4 hv = make_uint4(packh2(xv0.x, xv0.y), packh2(xv0.z, xv0.w),
                            packh2(xv1.x, xv1.y), packh2(xv1.z, xv1.w));
      uint32_t stg2 = ((uint32_t)(c + 1) & 1u) * PSTG;
      *(uint4*)(sm + stg2 + aoff) = hv;
    }
  }

  const int g = lane >> 2, t = lane & 3;
#pragma unroll
  for (int mi = 0; mi < 2; mi++) {
#pragma unroll
    for (int ni = 0; ni < 6; ni++) {
      int col = wn * 48 + ni * 8 + t * 2;
#pragma unroll
      for (int half = 0; half < 2; half++) {
        int row = blockIdx.x * 128 + wm * 32 + mi * 16 + g + half * 8;
        float a = acc[mi][ni][2 * half], b = acc[mi][ni][2 * half + 1];
        g_qkv32[(size_t)row * 96 + (col >> 1)] = packh2(a, b);
      }
    }
  }
}

// ---------------------------------------------------------------------------
// Kernel 2 v9: attn7 (R12) + scale folded into Q (HMUL2) + fp16x2 ex2
// softmax (pF = ex2 output directly) + diagonal warp-skip.
// ---------------------------------------------------------------------------
#define QS 0
#define ST0 8192
#define STAGE_SZ 16384           // K@+0, V@+8192
#define OBUF 0
#define LBUF 16384
#define ATT_SMEM (8192 + 2 * 16384)  // 40 KB

__global__ __launch_bounds__(256, 2) void attn9_kernel(float* __restrict__ out) {
  extern __shared__ char sm[];
  const uint32_t sb = smem_u32(sm);
  const int b    = blockIdx.x & 15;
  const int qt   = 31 - (blockIdx.x >> 4);  // heaviest first
  const int tid  = threadIdx.x;
  const int lane = tid & 31;
  const int wid  = tid >> 5;
  const int wm   = wid & 3;
  const int wn   = wid >> 2;
  const int g    = lane >> 2;
  const int t    = lane & 3;
  const float scale2 = 0.03125f * 1.44269504f;  // (1/sqrt(C)) * log2(e)

  const uint32_t relA_base = (uint32_t)(wm * 16 + ((lane >> 3) & 1) * 8 + (lane & 7)) * 128 +
                             ((lane >> 4) & 1) * 16;
  const uint32_t rowB_l = (uint32_t)(((lane >> 4) & 1) * 8 + (lane & 7));
  const uint32_t koffB  = ((lane >> 3) & 1) * 16;
  const uint32_t rowV_l = (uint32_t)(lane & 15);
  const uint32_t doffV  = ((lane >> 4) & 1) * 8;

  // ---- prologue: Q + K/V tile 0 ----
#pragma unroll
  for (int it = 0; it < 2; it++) {
    int idx = tid + 256 * it;
    int row = idx >> 3;
    int seg = idx & 7;
    const void* src = g_qkv32 + ((size_t)b * TT + qt * 64 + row) * 96 + seg * 4;
    cp16(sb + QS + swz((uint32_t)row * 128 + seg * 16), src);
  }
  const int pr  = tid >> 3;
  const int pseg = tid & 7;
  const uint32_t d0 = swz((uint32_t)pr * 128 + pseg * 16);
  const uint32_t d1 = swz((uint32_t)(pr + 32) * 128 + pseg * 16);
  const char* pf0 = (const char*)(g_qkv32 + ((size_t)b * TT + pr) * 96 + 32 + pseg * 4);
  {
    cp16(sb + ST0 + d0,         pf0);
    cp16(sb + ST0 + d1,         pf0 + 12288);
    cp16(sb + ST0 + 8192u + d0, pf0 + 128);
    cp16(sb + ST0 + 8192u + d1, pf0 + 12288 + 128);
  }
  CP_COMMIT();
  CP_WAIT0();
  __syncthreads();

  // ---- Q fragments to registers, pre-scaled by scale2 (fp16) ----
  uint32_t qF[4][4];
  {
    const __half2 sc2 = __floats2half2_rn(scale2, scale2);
#pragma unroll
    for (int kk = 0; kk < 4; kk++) {
      ldsm_x4(qF[kk], sb + QS + swz(relA_base + kk * 32));
#pragma unroll
      for (int i = 0; i < 4; i++) {
        __half2 v = __hmul2(*(__half2*)&qF[kk][i], sc2);
        qF[kk][i] = *(uint32_t*)&v;
      }
    }
  }

  const char* pf = pf0 + 24576;

  float o[8][4];
#pragma unroll
  for (int nb = 0; nb < 8; nb++)
#pragma unroll
    for (int j = 0; j < 4; j++) o[nb][j] = 0.0f;
  float lsum0 = 0.0f, lsum1 = 0.0f;

#pragma unroll 1
  for (int kt = 0; kt <= qt; kt++) {
    const bool more = (kt < qt);
    if (more) {
      const uint32_t stb2 = sb + ST0 + (uint32_t)((kt + 1) & 1) * STAGE_SZ;
      cp16(stb2 + d0,         pf);
      cp16(stb2 + d1,         pf + 12288);
      cp16(stb2 + 8192u + d0, pf + 128);
      cp16(stb2 + 8192u + d1, pf + 12288 + 128);
      CP_COMMIT();
      pf += 24576;
    }

    const bool diag  = (kt == qt);
    const bool skipw = diag && (wn == 1) && (wm < 2);  // 16x32 block fully masked
    if (!skipw) {
      const uint32_t stb = sb + ST0 + (uint32_t)(kt & 1) * STAGE_SZ;
      const uint32_t Ko = stb, Vo = stb + 8192u;

      // ---- Phase A: S = (Q*c) K^T (scale already folded) ----
      float sA[4][4];
#pragma unroll
      for (int nb = 0; nb < 4; nb++)
#pragma unroll
        for (int j = 0; j < 4; j++) sA[nb][j] = 0.0f;

#pragma unroll
      for (int kk = 0; kk < 4; kk++) {
#pragma unroll
        for (int nb2 = 0; nb2 < 2; nb2++) {
          uint32_t bF[4];
          uint32_t relB = swz((uint32_t)(wn * 32 + nb2 * 16 + rowB_l) * 128 + kk * 32 + koffB);
          ldsm_x4(bF, Ko + relB);
#pragma unroll
          for (int h = 0; h < 2; h++)
            mma_f16(sA[2 * nb2 + h], qF[kk], bF[2 * h], bF[2 * h + 1]);
        }
      }

      // ---- mask + fp16x2 exp2 + rowsum; pP = P fragments ready for MMA ----
      uint32_t pP[4][2];
#pragma unroll
      for (int nb = 0; nb < 4; nb++) {
        float s0 = sA[nb][0], s1 = sA[nb][1];
        float s2 = sA[nb][2], s3 = sA[nb][3];
        if (diag) {
          int colb = wn * 32 + nb * 8 + t * 2;
          int row0 = wm * 16 + g;
          if (colb     > row0)     s0 = -1e9f;
          if (colb + 1 > row0)     s1 = -1e9f;
          if (colb     > row0 + 8) s2 = -1e9f;
          if (colb + 1 > row0 + 8) s3 = -1e9f;
        }
        uint32_t e0 = ex2h2(packh2(s0, s1));
        uint32_t e1 = ex2h2(packh2(s2, s3));
        pP[nb][0] = e0;
        pP[nb][1] = e1;
        float2 f0 = __half22float2(*(__half2*)&e0);
        float2 f1 = __half22float2(*(__half2*)&e1);
        lsum0 += f0.x + f0.y;
        lsum1 += f1.x + f1.y;
      }

      // ---- Phase B: O += P V ----
#pragma unroll
      for (int kb = 0; kb < 2; kb++) {
        uint32_t pF[4];
        pF[0] = pP[2 * kb][0];
        pF[1] = pP[2 * kb][1];
        pF[2] = pP[2 * kb + 1][0];
        pF[3] = pP[2 * kb + 1][1];
#pragma unroll
        for (int dg = 0; dg < 4; dg++) {
          uint32_t vF[4];
          uint32_t relV = swz((uint32_t)(wn * 32 + kb * 16 + rowV_l) * 128 +
                              (dg * 16 + doffV) * 2);
          ldsm_x4_t(vF, Vo + relV);
#pragma unroll
          for (int h = 0; h < 2; h++)
            mma_f16(o[dg * 2 + h], pF, vF[2 * h], vF[2 * h + 1]);
        }
      }
    }

    if (more) {
      CP_WAIT0();
      __syncthreads();
    }
  }

  // ---- epilogue: combine key-halves, normalize, store ----
  lsum0 += __shfl_xor_sync(0xffffffffu, lsum0, 1);
  lsum0 += __shfl_xor_sync(0xffffffffu, lsum0, 2);
  lsum1 += __shfl_xor_sync(0xffffffffu, lsum1, 1);
  lsum1 += __shfl_xor_sync(0xffffffffu, lsum1, 2);

  __syncthreads();
  float* obuf = (float*)(sm + OBUF) + wm * 1024;
  float* lbuf = (float*)(sm + LBUF) + wm * 16;
  if (wn == 1) {
#pragma unroll
    for (int nb = 0; nb < 8; nb++) {
      int col = nb * 8 + t * 2;
      *(float2*)(obuf + g * 64 + col)       = make_float2(o[nb][0], o[nb][1]);
      *(float2*)(obuf + (g + 8) * 64 + col) = make_float2(o[nb][2], o[nb][3]);
    }
    if (t == 0) { lbuf[g] = lsum0; lbuf[g + 8] = lsum1; }
  }
  __syncthreads();
  if (wn == 0) {
    float inv0 = 1.0f / (lsum0 + lbuf[g]);
    float inv1 = 1.0f / (lsum1 + lbuf[g + 8]);
    size_t r0 = ((size_t)b * TT + qt * 64 + wm * 16 + g) * HH;
    size_t r1 = r0 + 8 * HH;
#pragma unroll
    for (int nb = 0; nb < 8; nb++) {
      int col = nb * 8 + t * 2;
      float2 pa = *(float2*)(obuf + g * 64 + col);
      float2 pb = *(float2*)(obuf + (g + 8) * 64 + col);
      *(float2*)(out + r0 + col) =
          make_float2((o[nb][0] + pa.x) * inv0, (o[nb][1] + pa.y) * inv0);
      *(float2*)(out + r1 + col) =
          make_float2((o[nb][2] + pb.x) * inv1, (o[nb][3] + pb.y) * inv1);
    }
  }
}

// ---------------------------------------------------------------------------
extern "C" void kernel_launch(void* const* d_in, const int* in_sizes, int n_in,
                              void* d_out, int out_size) {
  const float* x  = (const float*)d_in[0];
  const float* Wq = (const float*)d_in[1];
  const float* Wk = (const float*)d_in[2];
  const float* Wv = (const float*)d_in[3];
  float* out = (float*)d_out;

  cudaFuncSetAttribute(qkv_mma_kernel, cudaFuncAttributeMaxDynamicSharedMemorySize, PROJ_SMEM);
  cudaFuncSetAttribute(attn9_kernel, cudaFuncAttributeMaxDynamicSharedMemorySize, ATT_SMEM);

  wprep_kernel<<<192, 256>>>(Wq, Wk, Wv);
  qkv_mma_kernel<<<NROWS / 128, 512, PROJ_SMEM>>>(x);
  attn9_kernel<<<16 * 32, 256, ATT_SMEM>>>(out);
}